// round 12
// baseline (speedup 1.0000x reference)
#include <cuda_runtime.h>
#include <math.h>
#include <stdint.h>

#define L_   4
#define D_   512
#define H_   8
#define HD_  64
#define DFF_ 2048
#define B_   8
#define S_   1024
#define BS_  (B_*S_)   // 8192 rows

typedef unsigned long long u64;

// ---------------- scratch (device globals; no allocations allowed) ----------
__device__ float g_x [BS_*D_];     // residual stream (f32)
__device__ u64   g_hs[BS_*D_];     // packed-split LN / attention outputs
__device__ float g_q [BS_*D_];
__device__ float g_k [BS_*D_];
__device__ float g_v [BS_*D_];
__device__ u64   g_ffs[BS_*DFF_];  // packed-split FFN hidden
__device__ int   g_len[B_];

// packed-split weights: [Wq | Wk | Wv | Wo | W1 | W2], all L layers
#define WQ_SZ  (L_*D_*D_)          // 1048576
#define W1_SZ  (L_*D_*DFF_)        // 4194304
#define OFF_WQ 0
#define OFF_WK (OFF_WQ + WQ_SZ)
#define OFF_WV (OFF_WK + WQ_SZ)
#define OFF_WO (OFF_WV + WQ_SZ)
#define OFF_W1 (OFF_WO + WQ_SZ)
#define OFF_W2 (OFF_W1 + W1_SZ)
#define WS_TOT (OFF_W2 + W1_SZ)    // 12582912 elements (96MB)
__device__ u64 g_ws[WS_TOT];

// ---------------- split helpers ---------------------------------------------
__device__ __forceinline__ uint32_t f2tf32(float x) {
    uint32_t r;
    asm("cvt.rna.tf32.f32 %0, %1;" : "=r"(r) : "f"(x));
    return r;
}
__device__ __forceinline__ u64 pack_hl(float v) {
    uint32_t hi = f2tf32(v);
    uint32_t lo = f2tf32(v - __uint_as_float(hi));
    return ((u64)lo << 32) | (u64)hi;
}

// ---------------- weight split kernel (runs once per call) ------------------
__global__ __launch_bounds__(256) void split_kernel(const float* __restrict__ src,
                                                    u64* __restrict__ dst, int n) {
    int i = (blockIdx.x * 256 + threadIdx.x) * 4;
    if (i < n) {
        float4 v = *(const float4*)&src[i];
        dst[i + 0] = pack_hl(v.x);
        dst[i + 1] = pack_hl(v.y);
        dst[i + 2] = pack_hl(v.z);
        dst[i + 3] = pack_hl(v.w);
    }
}

// ---------------- mask length extraction ------------------------------------
__global__ __launch_bounds__(256) void masklen_kernel(const unsigned int* __restrict__ mask) {
    int b = blockIdx.x, t = threadIdx.x;
    int cnt = 0;
    for (int i = t; i < S_; i += 256) cnt += (mask[b * S_ + i] != 0u) ? 1 : 0;
    #pragma unroll
    for (int o = 16; o; o >>= 1) cnt += __shfl_xor_sync(0xffffffffu, cnt, o);
    __shared__ int sh[8];
    if ((t & 31) == 0) sh[t >> 5] = cnt;
    __syncthreads();
    if (t == 0) {
        int s = 0;
        #pragma unroll
        for (int w = 0; w < 8; w++) s += sh[w];
        g_len[b] = s;
    }
}

// ---------------- positional encoding ---------------------------------------
__global__ __launch_bounds__(512) void posenc_kernel(const float* __restrict__ x) {
    int s = blockIdx.x, b = blockIdx.y, d = threadIdx.x;
    float j = (float)((d < 256) ? d : d - 256);
    float inv = powf(10000.0f, (2.0f * j) / 512.0f);
    float ang = (float)s / inv;
    float pe  = (d < 256) ? sinf(ang) : cosf(ang);
    size_t idx = ((size_t)b * S_ + s) * D_ + d;
    g_x[idx] = x[idx] + pe;
}

// ---------------- layernorm -> packed split output --------------------------
__global__ __launch_bounds__(128) void ln_kernel(const float* __restrict__ in,
                                                 const float* __restrict__ gw,
                                                 const float* __restrict__ bw,
                                                 u64* __restrict__ out) {
    int row = blockIdx.x;
    int t = threadIdx.x;
    const float4* rp = (const float4*)(in + (size_t)row * D_);
    float4 v = rp[t];
    float s  = v.x + v.y + v.z + v.w;
    float sq = v.x*v.x + v.y*v.y + v.z*v.z + v.w*v.w;
    #pragma unroll
    for (int o = 16; o; o >>= 1) {
        s  += __shfl_xor_sync(0xffffffffu, s,  o);
        sq += __shfl_xor_sync(0xffffffffu, sq, o);
    }
    __shared__ float sh[8];
    int wid = t >> 5, lane = t & 31;
    if (lane == 0) { sh[wid] = s; sh[4 + wid] = sq; }
    __syncthreads();
    s  = sh[0] + sh[1] + sh[2] + sh[3];
    sq = sh[4] + sh[5] + sh[6] + sh[7];
    float mu  = s * (1.0f / D_);
    float var = sq * (1.0f / D_) - mu * mu;
    float r   = rsqrtf(var + 1e-3f);
    float4 gg = ((const float4*)gw)[t];
    float4 bb = ((const float4*)bw)[t];
    u64* op = out + (size_t)row * D_ + t * 4;
    op[0] = pack_hl((v.x - mu) * r * gg.x + bb.x);
    op[1] = pack_hl((v.y - mu) * r * gg.y + bb.y);
    op[2] = pack_hl((v.z - mu) * r * gg.z + bb.z);
    op[3] = pack_hl((v.w - mu) * r * gg.w + bb.w);
}

// ============================================================================
// Tensor-core GEMM on pre-split packed inputs.
// C = A(MxK) @ W(KxN) [+bias][relu][+resid][packed-out]
// BM=128, BN=64, BK=16; 256 threads = 8 warps; warp tile 32x32; 3xTF32.
// ============================================================================
#define BM 128
#define BN 64
#define BK 16

__device__ __forceinline__ void mma_tf32(float c[4], const uint32_t a[4], const uint32_t b[2]) {
    asm volatile(
        "mma.sync.aligned.m16n8k8.row.col.f32.tf32.tf32.f32 "
        "{%0,%1,%2,%3}, {%4,%5,%6,%7}, {%8,%9}, {%0,%1,%2,%3};\n"
        : "+f"(c[0]), "+f"(c[1]), "+f"(c[2]), "+f"(c[3])
        : "r"(a[0]), "r"(a[1]), "r"(a[2]), "r"(a[3]),
          "r"(b[0]), "r"(b[1]));
}

struct GemmSmem {
    u64 A[2][BK][BM];   // 32768 B
    u64 Bt[2][BK][BN];  // 16384 B   (total 48KB)
};

// FLAGS: bit0 = +bias, bit1 = relu, bit2 = +resid, bit3 = packed split output
template<int FLAGS>
__device__ __forceinline__ void gemm_core(const u64* __restrict__ A,
                                          const u64* __restrict__ W,
                                          const float* __restrict__ bias,
                                          const float* __restrict__ resid,
                                          void* __restrict__ Cv,
                                          int K, int N,
                                          int rowStart, int colStart,
                                          GemmSmem* sm) {
    int tid  = threadIdx.x;
    int warp = tid >> 5;
    int lane = tid & 31;
    int warpM = warp & 3;
    int warpN = warp >> 2;
    int gid = lane >> 2;
    int tig = lane & 3;
    int q   = tid & 3;

    float acc[2][4][4];
    #pragma unroll
    for (int mt = 0; mt < 2; mt++)
        #pragma unroll
        for (int nt = 0; nt < 4; nt++)
            #pragma unroll
            for (int r = 0; r < 4; r++) acc[mt][nt][r] = 0.0f;

    int a_r0 = tid >> 2;                // 0..63
    int a_k0 = q * 4;                   // 0,4,8,12
    int b_r  = tid >> 4;                // 0..15
    int b_c  = (tid & 15) * 4;

    ulonglong2 pa[2][2], pb[2];

    // ---- prologue load ----
    pa[0][0] = *(const ulonglong2*)&A[(size_t)(rowStart + a_r0) * K + a_k0];
    pa[0][1] = *(const ulonglong2*)&A[(size_t)(rowStart + a_r0) * K + a_k0 + 2];
    pa[1][0] = *(const ulonglong2*)&A[(size_t)(rowStart + a_r0 + 64) * K + a_k0];
    pa[1][1] = *(const ulonglong2*)&A[(size_t)(rowStart + a_r0 + 64) * K + a_k0 + 2];
    pb[0]    = *(const ulonglong2*)&W[(size_t)b_r * N + colStart + b_c];
    pb[1]    = *(const ulonglong2*)&W[(size_t)b_r * N + colStart + b_c + 2];

    int cur = 0;
    {
        #pragma unroll
        for (int i = 0; i < 2; i++) {
            int ar = a_r0 + i * 64;
            u64 vals[4] = {pa[i][0].x, pa[i][0].y, pa[i][1].x, pa[i][1].y};
            #pragma unroll
            for (int j = 0; j < 4; j++) {
                int jr = (j + q) & 3;             // lane rotation
                int row = a_k0 + jr;
                sm->A[0][row][ar ^ ((row & 3) << 2)] = vals[jr];
            }
        }
        u64 vb[4] = {pb[0].x, pb[0].y, pb[1].x, pb[1].y};
        #pragma unroll
        for (int j = 0; j < 4; j++) {
            int col = b_c + j;
            sm->Bt[0][b_r][col ^ ((b_r & 3) << 2)] = vb[j];
        }
    }
    __syncthreads();

    int m0 = warpM * 32;
    int n0 = warpN * 32;

    for (int k0 = BK; ; k0 += BK) {
        bool more = (k0 < K);
        if (more) {
            pa[0][0] = *(const ulonglong2*)&A[(size_t)(rowStart + a_r0) * K + k0 + a_k0];
            pa[0][1] = *(const ulonglong2*)&A[(size_t)(rowStart + a_r0) * K + k0 + a_k0 + 2];
            pa[1][0] = *(const ulonglong2*)&A[(size_t)(rowStart + a_r0 + 64) * K + k0 + a_k0];
            pa[1][1] = *(const ulonglong2*)&A[(size_t)(rowStart + a_r0 + 64) * K + k0 + a_k0 + 2];
            pb[0]    = *(const ulonglong2*)&W[(size_t)(k0 + b_r) * N + colStart + b_c];
            pb[1]    = *(const ulonglong2*)&W[(size_t)(k0 + b_r) * N + colStart + b_c + 2];
        }

        #pragma unroll
        for (int ks = 0; ks < 2; ks++) {
            int kb = ks * 8;
            int k1 = kb + tig, k2 = kb + tig + 4;
            int swz = tig << 2;
            uint32_t ah[2][4], al[2][4], bh[4][2], bl[4][2];
            #pragma unroll
            for (int mt = 0; mt < 2; mt++) {
                int mm = m0 + mt * 16;
                u64 e0 = sm->A[cur][k1][(mm + gid    ) ^ swz];
                u64 e1 = sm->A[cur][k1][(mm + gid + 8) ^ swz];
                u64 e2 = sm->A[cur][k2][(mm + gid    ) ^ swz];
                u64 e3 = sm->A[cur][k2][(mm + gid + 8) ^ swz];
                ah[mt][0] = (uint32_t)e0; al[mt][0] = (uint32_t)(e0 >> 32);
                ah[mt][1] = (uint32_t)e1; al[mt][1] = (uint32_t)(e1 >> 32);
                ah[mt][2] = (uint32_t)e2; al[mt][2] = (uint32_t)(e2 >> 32);
                ah[mt][3] = (uint32_t)e3; al[mt][3] = (uint32_t)(e3 >> 32);
            }
            #pragma unroll
            for (int nt = 0; nt < 4; nt++) {
                int nn = n0 + nt * 8;
                u64 f0 = sm->Bt[cur][k1][(nn + gid) ^ swz];
                u64 f1 = sm->Bt[cur][k2][(nn + gid) ^ swz];
                bh[nt][0] = (uint32_t)f0; bl[nt][0] = (uint32_t)(f0 >> 32);
                bh[nt][1] = (uint32_t)f1; bl[nt][1] = (uint32_t)(f1 >> 32);
            }
            #pragma unroll
            for (int mt = 0; mt < 2; mt++)
                #pragma unroll
                for (int nt = 0; nt < 4; nt++) {
                    mma_tf32(acc[mt][nt], ah[mt], bh[nt]);
                    mma_tf32(acc[mt][nt], ah[mt], bl[nt]);
                    mma_tf32(acc[mt][nt], al[mt], bh[nt]);
                }
        }
        if (!more) break;

        int nxt = cur ^ 1;
        #pragma unroll
        for (int i = 0; i < 2; i++) {
            int ar = a_r0 + i * 64;
            u64 vals[4] = {pa[i][0].x, pa[i][0].y, pa[i][1].x, pa[i][1].y};
            #pragma unroll
            for (int j = 0; j < 4; j++) {
                int jr = (j + q) & 3;
                int row = a_k0 + jr;
                sm->A[nxt][row][ar ^ ((row & 3) << 2)] = vals[jr];
            }
        }
        u64 vb[4] = {pb[0].x, pb[0].y, pb[1].x, pb[1].y};
        #pragma unroll
        for (int j = 0; j < 4; j++) {
            int col = b_c + j;
            sm->Bt[nxt][b_r][col ^ ((b_r & 3) << 2)] = vb[j];
        }
        __syncthreads();
        cur = nxt;
    }

    // ---- epilogue ----
    #pragma unroll
    for (int mt = 0; mt < 2; mt++) {
        #pragma unroll
        for (int half = 0; half < 2; half++) {
            int row = rowStart + m0 + mt * 16 + gid + half * 8;
            #pragma unroll
            for (int nt = 0; nt < 4; nt++) {
                int col = colStart + n0 + nt * 8 + tig * 2;
                size_t base = (size_t)row * N + col;
                float2 v;
                v.x = acc[mt][nt][half * 2 + 0];
                v.y = acc[mt][nt][half * 2 + 1];
                if (FLAGS & 1) {
                    float2 bb = *(const float2*)&bias[col];
                    v.x += bb.x; v.y += bb.y;
                }
                if (FLAGS & 2) {
                    v.x = fmaxf(v.x, 0.0f); v.y = fmaxf(v.y, 0.0f);
                }
                if (FLAGS & 4) {
                    float2 rr = *(const float2*)&resid[base];
                    v.x += rr.x; v.y += rr.y;
                }
                if (FLAGS & 8) {
                    u64* Cp = (u64*)Cv;
                    Cp[base + 0] = pack_hl(v.x);
                    Cp[base + 1] = pack_hl(v.y);
                } else {
                    *(float2*)&((float*)Cv)[base] = v;
                }
            }
        }
    }
}

template<int FLAGS>
__global__ __launch_bounds__(256, 2) void sgemm(const u64* __restrict__ A,
                                                const u64* __restrict__ W,
                                                const float* __restrict__ bias,
                                                const float* __restrict__ resid,
                                                void* __restrict__ C,
                                                int K, int N) {
    __shared__ GemmSmem sm;
    gemm_core<FLAGS>(A, W, bias, resid, C, K, N,
                     blockIdx.y * BM, blockIdx.x * BN, &sm);
}

// QKV fused: blockIdx.z selects weight/output
__global__ __launch_bounds__(256, 2) void sgemm_qkv(const u64* __restrict__ A,
                                                    const u64* __restrict__ w0,
                                                    const u64* __restrict__ w1,
                                                    const u64* __restrict__ w2,
                                                    float* __restrict__ c0,
                                                    float* __restrict__ c1,
                                                    float* __restrict__ c2) {
    __shared__ GemmSmem sm;
    const u64* W = (blockIdx.z == 0) ? w0 : (blockIdx.z == 1) ? w1 : w2;
    float*     C = (blockIdx.z == 0) ? c0 : (blockIdx.z == 1) ? c1 : c2;
    gemm_core<0>(A, W, nullptr, nullptr, C, D_, D_,
                 blockIdx.y * BM, blockIdx.x * BN, &sm);
}

// ---------------- flash attention (fp32, online softmax) --------------------
// Writes packed-split output directly (consumed by Wo GEMM).
__global__ __launch_bounds__(128) void attn_kernel() {
    int b = blockIdx.z, h = blockIdx.y;
    int r = blockIdx.x * 128 + threadIdx.x;
    int len = g_len[b];

    const float4* qp = (const float4*)(g_q + ((size_t)(b * S_ + r)) * D_ + h * HD_);
    float4 q[16];
    #pragma unroll
    for (int i = 0; i < 16; i++) q[i] = qp[i];

    float4 o[16];
    #pragma unroll
    for (int i = 0; i < 16; i++) o[i] = make_float4(0.f, 0.f, 0.f, 0.f);
    float m = -INFINITY, l = 0.0f;
    const float scale = 0.125f;

    __shared__ float4 k_s[64][16];
    __shared__ float4 v_s[64][16];

    for (int j0 = 0; j0 < len; j0 += 64) {
        int jmax = (len - j0 < 64) ? (len - j0) : 64;
        __syncthreads();
        #pragma unroll
        for (int i = 0; i < 8; i++) {
            int idx = threadIdx.x + i * 128;
            int row = idx >> 4, c = idx & 15;
            size_t gbase = ((size_t)(b * S_ + j0 + row)) * D_ + h * HD_;
            k_s[row][c] = ((const float4*)(g_k + gbase))[c];
            v_s[row][c] = ((const float4*)(g_v + gbase))[c];
        }
        __syncthreads();

        #pragma unroll 4
        for (int j = 0; j < jmax; j++) {
            float acc = 0.0f;
            #pragma unroll
            for (int i = 0; i < 16; i++) {
                float4 kk = k_s[j][i];
                acc += q[i].x * kk.x + q[i].y * kk.y + q[i].z * kk.z + q[i].w * kk.w;
            }
            float s = acc * scale;
            if (s <= m) {
                float p = expf(s - m);
                l += p;
                #pragma unroll
                for (int i = 0; i < 16; i++) {
                    float4 vv = v_s[j][i];
                    o[i].x += p * vv.x; o[i].y += p * vv.y;
                    o[i].z += p * vv.z; o[i].w += p * vv.w;
                }
            } else {
                float corr = expf(m - s);
                m = s;
                l = l * corr + 1.0f;
                #pragma unroll
                for (int i = 0; i < 16; i++) {
                    float4 vv = v_s[j][i];
                    o[i].x = o[i].x * corr + vv.x; o[i].y = o[i].y * corr + vv.y;
                    o[i].z = o[i].z * corr + vv.z; o[i].w = o[i].w * corr + vv.w;
                }
            }
        }
    }

    float inv = (l > 0.0f) ? (1.0f / l) : 0.0f;
    u64* op = g_hs + ((size_t)(b * S_ + r)) * D_ + h * HD_;
    #pragma unroll
    for (int i = 0; i < 16; i++) {
        float4 v = o[i];
        ulonglong2 p0, p1;
        p0.x = pack_hl(v.x * inv); p0.y = pack_hl(v.y * inv);
        p1.x = pack_hl(v.z * inv); p1.y = pack_hl(v.w * inv);
        *(ulonglong2*)&op[i * 4 + 0] = p0;
        *(ulonglong2*)&op[i * 4 + 2] = p1;
    }
}

// ---------------- launcher ---------------------------------------------------
extern "C" void kernel_launch(void* const* d_in, const int* in_sizes, int n_in,
                              void* d_out, int out_size) {
    const float* x    = (const float*)d_in[0];
    const unsigned int* mask = (const unsigned int*)d_in[1];
    const float* Wq   = (const float*)d_in[2];
    const float* Wk   = (const float*)d_in[3];
    const float* Wv   = (const float*)d_in[4];
    const float* Wo   = (const float*)d_in[5];
    const float* ln1g = (const float*)d_in[6];
    const float* ln1b = (const float*)d_in[7];
    const float* ln2g = (const float*)d_in[8];
    const float* ln2b = (const float*)d_in[9];
    const float* W1   = (const float*)d_in[10];
    const float* b1   = (const float*)d_in[11];
    const float* W2   = (const float*)d_in[12];
    const float* b2   = (const float*)d_in[13];

    float *px, *pq, *pk, *pv;
    u64 *phs, *pffs, *pws;
    cudaGetSymbolAddress((void**)&px,   g_x);
    cudaGetSymbolAddress((void**)&phs,  g_hs);
    cudaGetSymbolAddress((void**)&pq,   g_q);
    cudaGetSymbolAddress((void**)&pk,   g_k);
    cudaGetSymbolAddress((void**)&pv,   g_v);
    cudaGetSymbolAddress((void**)&pffs, g_ffs);
    cudaGetSymbolAddress((void**)&pws,  g_ws);

    // weight pre-split (once per call; pure bandwidth)
    split_kernel<<<WQ_SZ / 1024, 256>>>(Wq, pws + OFF_WQ, WQ_SZ);
    split_kernel<<<WQ_SZ / 1024, 256>>>(Wk, pws + OFF_WK, WQ_SZ);
    split_kernel<<<WQ_SZ / 1024, 256>>>(Wv, pws + OFF_WV, WQ_SZ);
    split_kernel<<<WQ_SZ / 1024, 256>>>(Wo, pws + OFF_WO, WQ_SZ);
    split_kernel<<<W1_SZ / 1024, 256>>>(W1, pws + OFF_W1, W1_SZ);
    split_kernel<<<W1_SZ / 1024, 256>>>(W2, pws + OFF_W2, W1_SZ);

    masklen_kernel<<<B_, 256>>>(mask);
    posenc_kernel<<<dim3(S_, B_), 512>>>(x);

    for (int l = 0; l < L_; l++) {
        const u64* wq = pws + OFF_WQ + (size_t)l * D_ * D_;
        const u64* wk = pws + OFF_WK + (size_t)l * D_ * D_;
        const u64* wv = pws + OFF_WV + (size_t)l * D_ * D_;
        const u64* wo = pws + OFF_WO + (size_t)l * D_ * D_;
        const u64* w1 = pws + OFF_W1 + (size_t)l * D_ * DFF_;
        const u64* w2 = pws + OFF_W2 + (size_t)l * DFF_ * D_;

        ln_kernel<<<BS_, 128>>>(px, ln1g + l * D_, ln1b + l * D_, phs);

        sgemm_qkv<<<dim3(D_ / BN, BS_ / BM, 3), 256>>>(phs, wq, wk, wv, pq, pk, pv);

        attn_kernel<<<dim3(S_ / 128, H_, B_), 128>>>();

        // x = x + attn_out @ Wo
        sgemm<4><<<dim3(D_ / BN, BS_ / BM), 256>>>(phs, wo, nullptr, px, px, D_, D_);

        ln_kernel<<<BS_, 128>>>(px, ln2g + l * D_, ln2b + l * D_, phs);

        // ff = relu(h @ W1 + b1)  -> packed split output
        sgemm<11><<<dim3(DFF_ / BN, BS_ / BM), 256>>>(phs, w1, b1 + (size_t)l * DFF_,
                                                      nullptr, pffs, D_, DFF_);
        // x = x + ff @ W2 + b2
        sgemm<5><<<dim3(D_ / BN, BS_ / BM), 256>>>(pffs, w2, b2 + (size_t)l * D_,
                                                   px, px, DFF_, D_);
    }

    cudaMemcpyAsync(d_out, px, sizeof(float) * BS_ * D_, cudaMemcpyDeviceToDevice);
}

// round 14
// speedup vs baseline: 1.3204x; 1.3204x over previous
#include <cuda_runtime.h>
#include <cuda_bf16.h>
#include <math.h>
#include <stdint.h>

#define L_   4
#define D_   512
#define H_   8
#define HD_  64
#define DFF_ 2048
#define B_   8
#define S_   1024
#define BS_  (B_*S_)

typedef unsigned long long u64;
typedef uint32_t u32;

// ---------------- scratch (device globals) -----------------------------------
__device__ float g_x [BS_*D_];     // residual stream (f32)
__device__ u32   g_hs[BS_*D_];     // packed bf16 hi|lo<<16: LN out / attn out
__device__ float g_q [BS_*D_];
__device__ float g_k [BS_*D_];
__device__ float g_v [BS_*D_];
__device__ u32   g_ffs[BS_*DFF_];  // packed FFN hidden
__device__ int   g_len[B_];

// packed+transposed weights Wt[N][K]: [Wq|Wk|Wv|Wo|W1|W2]
#define WQ_SZ  (L_*D_*D_)
#define W1_SZ  (L_*D_*DFF_)
#define OFF_WQ 0
#define OFF_WK (OFF_WQ + WQ_SZ)
#define OFF_WV (OFF_WK + WQ_SZ)
#define OFF_WO (OFF_WV + WQ_SZ)
#define OFF_W1 (OFF_WO + WQ_SZ)
#define OFF_W2 (OFF_W1 + W1_SZ)
#define WS_TOT (OFF_W2 + W1_SZ)
__device__ u32 g_ws[WS_TOT];

// ---------------- bf16 hi/lo pack --------------------------------------------
__device__ __forceinline__ u32 pack_bf(float v) {
    __nv_bfloat16 h = __float2bfloat16(v);
    float r = v - __bfloat162float(h);
    __nv_bfloat16 l = __float2bfloat16(r);
    return (u32)__bfloat16_as_ushort(h) | ((u32)__bfloat16_as_ushort(l) << 16);
}

// ---------------- weight transpose + split: src[K][N]f32 -> dst[N][K]u32 ----
__global__ __launch_bounds__(256) void splitT_kernel(const float* __restrict__ src,
                                                     u32* __restrict__ dst,
                                                     int K, int N) {
    __shared__ float t[32][33];
    const float* s = src + (size_t)blockIdx.z * K * N;
    u32* d = dst + (size_t)blockIdx.z * K * N;
    int n0 = blockIdx.x * 32, k0 = blockIdx.y * 32;
    int tx = threadIdx.x & 31, ty = (threadIdx.x >> 5) * 4;
    #pragma unroll
    for (int i = 0; i < 4; i++)
        t[ty + i][tx] = s[(size_t)(k0 + ty + i) * N + n0 + tx];
    __syncthreads();
    #pragma unroll
    for (int i = 0; i < 4; i++)
        d[(size_t)(n0 + ty + i) * K + k0 + tx] = pack_bf(t[tx][ty + i]);
}

// ---------------- mask length extraction -------------------------------------
__global__ __launch_bounds__(256) void masklen_kernel(const unsigned int* __restrict__ mask) {
    int b = blockIdx.x, t = threadIdx.x;
    int cnt = 0;
    for (int i = t; i < S_; i += 256) cnt += (mask[b * S_ + i] != 0u) ? 1 : 0;
    #pragma unroll
    for (int o = 16; o; o >>= 1) cnt += __shfl_xor_sync(0xffffffffu, cnt, o);
    __shared__ int sh[8];
    if ((t & 31) == 0) sh[t >> 5] = cnt;
    __syncthreads();
    if (t == 0) {
        int s = 0;
        #pragma unroll
        for (int w = 0; w < 8; w++) s += sh[w];
        g_len[b] = s;
    }
}

// ---------------- positional encoding ----------------------------------------
__global__ __launch_bounds__(512) void posenc_kernel(const float* __restrict__ x) {
    int s = blockIdx.x, b = blockIdx.y, d = threadIdx.x;
    float j = (float)((d < 256) ? d : d - 256);
    float inv = powf(10000.0f, (2.0f * j) / 512.0f);
    float ang = (float)s / inv;
    float pe  = (d < 256) ? sinf(ang) : cosf(ang);
    size_t idx = ((size_t)b * S_ + s) * D_ + d;
    g_x[idx] = x[idx] + pe;
}

// ---------------- layernorm -> packed bf16 hi/lo -----------------------------
__global__ __launch_bounds__(128) void ln_kernel(const float* __restrict__ in,
                                                 const float* __restrict__ gw,
                                                 const float* __restrict__ bw,
                                                 u32* __restrict__ out) {
    int row = blockIdx.x;
    int t = threadIdx.x;
    const float4* rp = (const float4*)(in + (size_t)row * D_);
    float4 v = rp[t];
    float s  = v.x + v.y + v.z + v.w;
    float sq = v.x*v.x + v.y*v.y + v.z*v.z + v.w*v.w;
    #pragma unroll
    for (int o = 16; o; o >>= 1) {
        s  += __shfl_xor_sync(0xffffffffu, s,  o);
        sq += __shfl_xor_sync(0xffffffffu, sq, o);
    }
    __shared__ float sh[8];
    int wid = t >> 5, lane = t & 31;
    if (lane == 0) { sh[wid] = s; sh[4 + wid] = sq; }
    __syncthreads();
    s  = sh[0] + sh[1] + sh[2] + sh[3];
    sq = sh[4] + sh[5] + sh[6] + sh[7];
    float mu  = s * (1.0f / D_);
    float var = sq * (1.0f / D_) - mu * mu;
    float r   = rsqrtf(var + 1e-3f);
    float4 gg = ((const float4*)gw)[t];
    float4 bb = ((const float4*)bw)[t];
    uint4 o;
    o.x = pack_bf((v.x - mu) * r * gg.x + bb.x);
    o.y = pack_bf((v.y - mu) * r * gg.y + bb.y);
    o.z = pack_bf((v.z - mu) * r * gg.z + bb.z);
    o.w = pack_bf((v.w - mu) * r * gg.w + bb.w);
    *(uint4*)(out + (size_t)row * D_ + t * 4) = o;
}

// ============================================================================
// bf16x3 tensor-core GEMM via mma.sync.m16n8k16.
// C[M,N] = A[M,K] @ Wt[N,K]^T; A, Wt packed u32 (bf16 hi | lo<<16).
// BM=128, BN=64, BK=32; 256 threads, 8 warps, warp tile 32x32.
// SMEM holds k-pair u32s: hi-pairs and lo-pairs in separate arrays.
// FLAGS: bit0=+bias, bit1=relu, bit2=+resid, bit3=packed out
// ============================================================================
#define BM 128
#define BN 64
#define BK 32
#define LDA3 136    // stride mod 32 == 8 -> conflict-free fragment LDS
#define LDB3 72

struct Stage {
    u32 Ah[BK/2][LDA3];
    u32 Al[BK/2][LDA3];
    u32 Bh[BK/2][LDB3];
    u32 Bl[BK/2][LDB3];
};
#define SMEMSZ (2 * (int)sizeof(Stage))

__device__ __forceinline__ void mma_bf16(float c[4], const u32 a[4], const u32 b[2]) {
    asm volatile(
        "mma.sync.aligned.m16n8k16.row.col.f32.bf16.bf16.f32 "
        "{%0,%1,%2,%3}, {%4,%5,%6,%7}, {%8,%9}, {%0,%1,%2,%3};\n"
        : "+f"(c[0]), "+f"(c[1]), "+f"(c[2]), "+f"(c[3])
        : "r"(a[0]), "r"(a[1]), "r"(a[2]), "r"(a[3]),
          "r"(b[0]), "r"(b[1]));
}

template<int FLAGS>
__device__ __forceinline__ void gemm_core(const u32* __restrict__ A,
                                          const u32* __restrict__ Wt,
                                          const float* __restrict__ bias,
                                          const float* __restrict__ resid,
                                          void* __restrict__ Cv,
                                          int K, int N,
                                          int rowStart, int colStart) {
    extern __shared__ Stage stg[];   // stg[0], stg[1]

    int tid  = threadIdx.x;
    int wid  = tid >> 5;
    int lane = tid & 31;
    int warpM = wid & 3;
    int warpN = wid >> 2;
    int gid = lane >> 2;       // 0..7
    int tig = lane & 3;        // 0..3

    float acc[2][4][4];
    #pragma unroll
    for (int mt = 0; mt < 2; mt++)
        #pragma unroll
        for (int nt = 0; nt < 4; nt++)
            #pragma unroll
            for (int r = 0; r < 4; r++) acc[mt][nt][r] = 0.0f;

    // load-task geometry (per warp-instruction: fixed k-group, 32 distinct rows)
    uint4 pa[4], pb[2];

    // ---- prologue: load chunk 0 into regs ----
    #pragma unroll
    for (int i = 0; i < 4; i++) {
        int task = i * 8 + wid;
        int f4 = task & 7, row = ((task >> 3) << 5) + lane;
        pa[i] = *(const uint4*)&A[(size_t)(rowStart + row) * K + f4 * 4];
    }
    #pragma unroll
    for (int i = 0; i < 2; i++) {
        int task = i * 8 + wid;
        int f4 = task & 7, n = ((task >> 3) << 5) + lane;
        pb[i] = *(const uint4*)&Wt[(size_t)(colStart + n) * K + f4 * 4];
    }

    int cur = 0;
    // ---- store prologue to stage 0 ----
    {
        Stage* st = &stg[0];
        #pragma unroll
        for (int i = 0; i < 4; i++) {
            int task = i * 8 + wid;
            int f4 = task & 7, row = ((task >> 3) << 5) + lane;
            int kp = f4 * 2;
            st->Ah[kp    ][row] = __byte_perm(pa[i].x, pa[i].y, 0x5410);
            st->Al[kp    ][row] = __byte_perm(pa[i].x, pa[i].y, 0x7632);
            st->Ah[kp + 1][row] = __byte_perm(pa[i].z, pa[i].w, 0x5410);
            st->Al[kp + 1][row] = __byte_perm(pa[i].z, pa[i].w, 0x7632);
        }
        #pragma unroll
        for (int i = 0; i < 2; i++) {
            int task = i * 8 + wid;
            int f4 = task & 7, n = ((task >> 3) << 5) + lane;
            int kp = f4 * 2;
            st->Bh[kp    ][n] = __byte_perm(pb[i].x, pb[i].y, 0x5410);
            st->Bl[kp    ][n] = __byte_perm(pb[i].x, pb[i].y, 0x7632);
            st->Bh[kp + 1][n] = __byte_perm(pb[i].z, pb[i].w, 0x5410);
            st->Bl[kp + 1][n] = __byte_perm(pb[i].z, pb[i].w, 0x7632);
        }
    }
    __syncthreads();

    int m0 = warpM * 32;
    int n0 = warpN * 32;

    for (int k0 = BK; ; k0 += BK) {
        bool more = (k0 < K);
        if (more) {
            #pragma unroll
            for (int i = 0; i < 4; i++) {
                int task = i * 8 + wid;
                int f4 = task & 7, row = ((task >> 3) << 5) + lane;
                pa[i] = *(const uint4*)&A[(size_t)(rowStart + row) * K + k0 + f4 * 4];
            }
            #pragma unroll
            for (int i = 0; i < 2; i++) {
                int task = i * 8 + wid;
                int f4 = task & 7, n = ((task >> 3) << 5) + lane;
                pb[i] = *(const uint4*)&Wt[(size_t)(colStart + n) * K + k0 + f4 * 4];
            }
        }

        // ---- compute on stage cur: 2 k16-steps ----
        Stage* st = &stg[cur];
        #pragma unroll
        for (int ks = 0; ks < 2; ks++) {
            int kA = ks * 8;
            u32 ah[2][4], al[2][4], bh[4][2], bl[4][2];
            #pragma unroll
            for (int mt = 0; mt < 2; mt++) {
                int m = m0 + mt * 16 + gid;
                ah[mt][0] = st->Ah[kA + tig    ][m];
                ah[mt][1] = st->Ah[kA + tig    ][m + 8];
                ah[mt][2] = st->Ah[kA + tig + 4][m];
                ah[mt][3] = st->Ah[kA + tig + 4][m + 8];
                al[mt][0] = st->Al[kA + tig    ][m];
                al[mt][1] = st->Al[kA + tig    ][m + 8];
                al[mt][2] = st->Al[kA + tig + 4][m];
                al[mt][3] = st->Al[kA + tig + 4][m + 8];
            }
            #pragma unroll
            for (int nt = 0; nt < 4; nt++) {
                int n = n0 + nt * 8 + gid;
                bh[nt][0] = st->Bh[kA + tig    ][n];
                bh[nt][1] = st->Bh[kA + tig + 4][n];
                bl[nt][0] = st->Bl[kA + tig    ][n];
                bl[nt][1] = st->Bl[kA + tig + 4][n];
            }
            #pragma unroll
            for (int mt = 0; mt < 2; mt++)
                #pragma unroll
                for (int nt = 0; nt < 4; nt++) {
                    mma_bf16(acc[mt][nt], ah[mt], bh[nt]);
                    mma_bf16(acc[mt][nt], ah[mt], bl[nt]);
                    mma_bf16(acc[mt][nt], al[mt], bh[nt]);
                }
        }
        if (!more) break;

        // ---- store prefetched chunk to other stage ----
        Stage* sn = &stg[cur ^ 1];
        #pragma unroll
        for (int i = 0; i < 4; i++) {
            int task = i * 8 + wid;
            int f4 = task & 7, row = ((task >> 3) << 5) + lane;
            int kp = f4 * 2;
            sn->Ah[kp    ][row] = __byte_perm(pa[i].x, pa[i].y, 0x5410);
            sn->Al[kp    ][row] = __byte_perm(pa[i].x, pa[i].y, 0x7632);
            sn->Ah[kp + 1][row] = __byte_perm(pa[i].z, pa[i].w, 0x5410);
            sn->Al[kp + 1][row] = __byte_perm(pa[i].z, pa[i].w, 0x7632);
        }
        #pragma unroll
        for (int i = 0; i < 2; i++) {
            int task = i * 8 + wid;
            int f4 = task & 7, n = ((task >> 3) << 5) + lane;
            int kp = f4 * 2;
            sn->Bh[kp    ][n] = __byte_perm(pb[i].x, pb[i].y, 0x5410);
            sn->Bl[kp    ][n] = __byte_perm(pb[i].x, pb[i].y, 0x7632);
            sn->Bh[kp + 1][n] = __byte_perm(pb[i].z, pb[i].w, 0x5410);
            sn->Bl[kp + 1][n] = __byte_perm(pb[i].z, pb[i].w, 0x7632);
        }
        __syncthreads();
        cur ^= 1;
    }

    // ---- epilogue ----
    #pragma unroll
    for (int mt = 0; mt < 2; mt++) {
        #pragma unroll
        for (int half = 0; half < 2; half++) {
            int row = rowStart + m0 + mt * 16 + gid + half * 8;
            #pragma unroll
            for (int nt = 0; nt < 4; nt++) {
                int col = colStart + n0 + nt * 8 + tig * 2;
                size_t base = (size_t)row * N + col;
                float2 v;
                v.x = acc[mt][nt][half * 2 + 0];
                v.y = acc[mt][nt][half * 2 + 1];
                if (FLAGS & 1) {
                    float2 bb = *(const float2*)&bias[col];
                    v.x += bb.x; v.y += bb.y;
                }
                if (FLAGS & 2) {
                    v.x = fmaxf(v.x, 0.0f); v.y = fmaxf(v.y, 0.0f);
                }
                if (FLAGS & 4) {
                    float2 rr = *(const float2*)&resid[base];
                    v.x += rr.x; v.y += rr.y;
                }
                if (FLAGS & 8) {
                    u32* Cp = (u32*)Cv;
                    Cp[base + 0] = pack_bf(v.x);
                    Cp[base + 1] = pack_bf(v.y);
                } else {
                    *(float2*)&((float*)Cv)[base] = v;
                }
            }
        }
    }
}

template<int FLAGS>
__global__ __launch_bounds__(256, 2) void gemm_tc(const u32* __restrict__ A,
                                                  const u32* __restrict__ Wt,
                                                  const float* __restrict__ bias,
                                                  const float* __restrict__ resid,
                                                  void* __restrict__ C,
                                                  int K, int N) {
    gemm_core<FLAGS>(A, Wt, bias, resid, C, K, N,
                     blockIdx.y * BM, blockIdx.x * BN);
}

__global__ __launch_bounds__(256, 2) void gemm_tc_qkv(const u32* __restrict__ A,
                                                      const u32* __restrict__ w0,
                                                      const u32* __restrict__ w1,
                                                      const u32* __restrict__ w2,
                                                      float* __restrict__ c0,
                                                      float* __restrict__ c1,
                                                      float* __restrict__ c2) {
    const u32* W = (blockIdx.z == 0) ? w0 : (blockIdx.z == 1) ? w1 : w2;
    float*     C = (blockIdx.z == 0) ? c0 : (blockIdx.z == 1) ? c1 : c2;
    gemm_core<0>(A, W, nullptr, nullptr, C, D_, D_,
                 blockIdx.y * BM, blockIdx.x * BN);
}

// ---------------- flash attention (fp32) -> packed bf16 out ------------------
__global__ __launch_bounds__(128) void attn_kernel() {
    int b = blockIdx.z, h = blockIdx.y;
    int r = blockIdx.x * 128 + threadIdx.x;
    int len = g_len[b];

    const float4* qp = (const float4*)(g_q + ((size_t)(b * S_ + r)) * D_ + h * HD_);
    float4 q[16];
    #pragma unroll
    for (int i = 0; i < 16; i++) q[i] = qp[i];

    float4 o[16];
    #pragma unroll
    for (int i = 0; i < 16; i++) o[i] = make_float4(0.f, 0.f, 0.f, 0.f);
    float m = -INFINITY, l = 0.0f;
    const float scale = 0.125f;

    __shared__ float4 k_s[64][16];
    __shared__ float4 v_s[64][16];

    for (int j0 = 0; j0 < len; j0 += 64) {
        int jmax = (len - j0 < 64) ? (len - j0) : 64;
        __syncthreads();
        #pragma unroll
        for (int i = 0; i < 8; i++) {
            int idx = threadIdx.x + i * 128;
            int row = idx >> 4, c = idx & 15;
            size_t gbase = ((size_t)(b * S_ + j0 + row)) * D_ + h * HD_;
            k_s[row][c] = ((const float4*)(g_k + gbase))[c];
            v_s[row][c] = ((const float4*)(g_v + gbase))[c];
        }
        __syncthreads();

        #pragma unroll 4
        for (int j = 0; j < jmax; j++) {
            float acc = 0.0f;
            #pragma unroll
            for (int i = 0; i < 16; i++) {
                float4 kk = k_s[j][i];
                acc += q[i].x * kk.x + q[i].y * kk.y + q[i].z * kk.z + q[i].w * kk.w;
            }
            float s = acc * scale;
            if (s <= m) {
                float p = expf(s - m);
                l += p;
                #pragma unroll
                for (int i = 0; i < 16; i++) {
                    float4 vv = v_s[j][i];
                    o[i].x += p * vv.x; o[i].y += p * vv.y;
                    o[i].z += p * vv.z; o[i].w += p * vv.w;
                }
            } else {
                float corr = expf(m - s);
                m = s;
                l = l * corr + 1.0f;
                #pragma unroll
                for (int i = 0; i < 16; i++) {
                    float4 vv = v_s[j][i];
                    o[i].x = o[i].x * corr + vv.x; o[i].y = o[i].y * corr + vv.y;
                    o[i].z = o[i].z * corr + vv.z; o[i].w = o[i].w * corr + vv.w;
                }
            }
        }
    }

    float inv = (l > 0.0f) ? (1.0f / l) : 0.0f;
    u32* op = g_hs + ((size_t)(b * S_ + r)) * D_ + h * HD_;
    #pragma unroll
    for (int i = 0; i < 16; i++) {
        float4 v = o[i];
        uint4 p = make_uint4(pack_bf(v.x * inv), pack_bf(v.y * inv),
                             pack_bf(v.z * inv), pack_bf(v.w * inv));
        *(uint4*)&op[i * 4] = p;
    }
}

// ---------------- launcher ---------------------------------------------------
extern "C" void kernel_launch(void* const* d_in, const int* in_sizes, int n_in,
                              void* d_out, int out_size) {
    const float* x    = (const float*)d_in[0];
    const unsigned int* mask = (const unsigned int*)d_in[1];
    const float* Wq   = (const float*)d_in[2];
    const float* Wk   = (const float*)d_in[3];
    const float* Wv   = (const float*)d_in[4];
    const float* Wo   = (const float*)d_in[5];
    const float* ln1g = (const float*)d_in[6];
    const float* ln1b = (const float*)d_in[7];
    const float* ln2g = (const float*)d_in[8];
    const float* ln2b = (const float*)d_in[9];
    const float* W1   = (const float*)d_in[10];
    const float* b1   = (const float*)d_in[11];
    const float* W2   = (const float*)d_in[12];
    const float* b2   = (const float*)d_in[13];

    float *px, *pq, *pk, *pv;
    u32 *phs, *pffs, *pws;
    cudaGetSymbolAddress((void**)&px,   g_x);
    cudaGetSymbolAddress((void**)&phs,  g_hs);
    cudaGetSymbolAddress((void**)&pq,   g_q);
    cudaGetSymbolAddress((void**)&pk,   g_k);
    cudaGetSymbolAddress((void**)&pv,   g_v);
    cudaGetSymbolAddress((void**)&pffs, g_ffs);
    cudaGetSymbolAddress((void**)&pws,  g_ws);

    cudaFuncSetAttribute(gemm_tc<4>,  cudaFuncAttributeMaxDynamicSharedMemorySize, SMEMSZ);
    cudaFuncSetAttribute(gemm_tc<11>, cudaFuncAttributeMaxDynamicSharedMemorySize, SMEMSZ);
    cudaFuncSetAttribute(gemm_tc<5>,  cudaFuncAttributeMaxDynamicSharedMemorySize, SMEMSZ);
    cudaFuncSetAttribute(gemm_tc_qkv, cudaFuncAttributeMaxDynamicSharedMemorySize, SMEMSZ);

    // weight transpose+split: src[K][N] f32 -> dst[N][K] packed u32
    splitT_kernel<<<dim3(D_/32,  D_/32,  L_), 256>>>(Wq, pws + OFF_WQ, D_, D_);
    splitT_kernel<<<dim3(D_/32,  D_/32,  L_), 256>>>(Wk, pws + OFF_WK, D_, D_);
    splitT_kernel<<<dim3(D_/32,  D_/32,  L_), 256>>>(Wv, pws + OFF_WV, D_, D_);
    splitT_kernel<<<dim3(D_/32,  D_/32,  L_), 256>>>(Wo, pws + OFF_WO, D_, D_);
    splitT_kernel<<<dim3(DFF_/32, D_/32, L_), 256>>>(W1, pws + OFF_W1, D_, DFF_);
    splitT_kernel<<<dim3(D_/32, DFF_/32, L_), 256>>>(W2, pws + OFF_W2, DFF_, D_);

    masklen_kernel<<<B_, 256>>>(mask);
    posenc_kernel<<<dim3(S_, B_), 512>>>(x);

    for (int l = 0; l < L_; l++) {
        const u32* wq = pws + OFF_WQ + (size_t)l * D_ * D_;
        const u32* wk = pws + OFF_WK + (size_t)l * D_ * D_;
        const u32* wv = pws + OFF_WV + (size_t)l * D_ * D_;
        const u32* wo = pws + OFF_WO + (size_t)l * D_ * D_;
        const u32* w1 = pws + OFF_W1 + (size_t)l * D_ * DFF_;
        const u32* w2 = pws + OFF_W2 + (size_t)l * DFF_ * D_;

        ln_kernel<<<BS_, 128>>>(px, ln1g + l * D_, ln1b + l * D_, phs);

        gemm_tc_qkv<<<dim3(D_/BN, BS_/BM, 3), 256, SMEMSZ>>>(phs, wq, wk, wv, pq, pk, pv);

        attn_kernel<<<dim3(S_/128, H_, B_), 128>>>();

        // x = x + attn_out @ Wo
        gemm_tc<4><<<dim3(D_/BN, BS_/BM), 256, SMEMSZ>>>(phs, wo, nullptr, px, px, D_, D_);

        ln_kernel<<<BS_, 128>>>(px, ln2g + l * D_, ln2b + l * D_, phs);

        // ff = relu(h @ W1 + b1) -> packed
        gemm_tc<11><<<dim3(DFF_/BN, BS_/BM), 256, SMEMSZ>>>(phs, w1, b1 + (size_t)l * DFF_,
                                                            nullptr, pffs, D_, DFF_);
        // x = x + ff @ W2 + b2
        gemm_tc<5><<<dim3(D_/BN, BS_/BM), 256, SMEMSZ>>>(pffs, w2, b2 + (size_t)l * D_,
                                                         px, px, DFF_, D_);
    }

    cudaMemcpyAsync(d_out, px, sizeof(float) * BS_ * D_, cudaMemcpyDeviceToDevice);
}